// round 15
// baseline (speedup 1.0000x reference)
#include <cuda_runtime.h>
#include <cuda_fp16.h>
#include <cstdint>
#include <math.h>

#define D_MODEL 1024
#define NHEADS 16
#define HD 64
#define BATCH 2
#define SEQ 2048
#define NTOK (BATCH * SEQ)   // 4096

// Q pre-scale: (1/sqrt(64)) * log2(e)  -> scores in log2 domain
#define QSCALE 0.180336875967866f

// ---------------------------------------------------------------------------
// Scratch (no allocations allowed)
// ---------------------------------------------------------------------------
__device__ __half g_x16[(size_t)NTOK * D_MODEL];
__device__ __half g_q16[(size_t)NTOK * D_MODEL];   // [B,H,S,hd] fp16, scaled
__device__ __half g_k16[(size_t)NTOK * D_MODEL];
__device__ __half g_v16[(size_t)NTOK * D_MODEL];
__device__ __half g_ct16[(size_t)NTOK * D_MODEL];  // ctx fp16 flat
__device__ __half g_w16[(size_t)4 * D_MODEL * D_MODEL];  // [n][k] fp16

// ---------------------------------------------------------------------------
// Helpers
// ---------------------------------------------------------------------------
__device__ __forceinline__ uint32_t smem_u32(const void* p) {
    uint32_t a;
    asm("{ .reg .u64 t; cvta.to.shared.u64 t, %1; cvt.u32.u64 %0, t; }" : "=r"(a) : "l"(p));
    return a;
}
__device__ __forceinline__ void cpa16(uint32_t s, const void* g) {
    asm volatile("cp.async.cg.shared.global [%0], [%1], 16;" :: "r"(s), "l"(g));
}
#define CP_COMMIT() asm volatile("cp.async.commit_group;" ::: "memory")
#define CP_WAIT2()  asm volatile("cp.async.wait_group 2;" ::: "memory")
#define CP_WAIT1()  asm volatile("cp.async.wait_group 1;" ::: "memory")
#define CP_WAIT0()  asm volatile("cp.async.wait_group 0;" ::: "memory")

#define LDMX4(r, a) \
    asm volatile("ldmatrix.sync.aligned.m8n8.x4.shared.b16 {%0,%1,%2,%3}, [%4];" \
        : "=r"((r)[0]), "=r"((r)[1]), "=r"((r)[2]), "=r"((r)[3]) : "r"(a))
#define LDMX4T(r, a) \
    asm volatile("ldmatrix.sync.aligned.m8n8.x4.trans.shared.b16 {%0,%1,%2,%3}, [%4];" \
        : "=r"((r)[0]), "=r"((r)[1]), "=r"((r)[2]), "=r"((r)[3]) : "r"(a))

__device__ __forceinline__ void mma16816h(float* c, const uint32_t* a, uint32_t b0, uint32_t b1) {
    asm volatile(
        "mma.sync.aligned.m16n8k16.row.col.f32.f16.f16.f32 "
        "{%0,%1,%2,%3}, {%4,%5,%6,%7}, {%8,%9}, {%0,%1,%2,%3};"
        : "+f"(c[0]), "+f"(c[1]), "+f"(c[2]), "+f"(c[3])
        : "r"(a[0]), "r"(a[1]), "r"(a[2]), "r"(a[3]), "r"(b0), "r"(b1));
}

__device__ __forceinline__ uint32_t packh(float lo, float hi) {
    uint32_t r;
    asm("cvt.rn.f16x2.f32 %0, %1, %2;" : "=r"(r) : "f"(hi), "f"(lo));
    return r;
}
__device__ __forceinline__ float ex2f(float x) {
    float y;
    asm("ex2.approx.f32 %0, %1;" : "=f"(y) : "f"(x));
    return y;
}

// ---------------------------------------------------------------------------
// Conversion kernels
// ---------------------------------------------------------------------------
__global__ void cvt16_kernel(const float* __restrict__ s, __half* __restrict__ d, int n) {
    int i = blockIdx.x * blockDim.x + threadIdx.x;
    int stride = gridDim.x * blockDim.x;
    for (int j = i * 2; j < n; j += stride * 2) {
        float2 v = *(const float2*)(s + j);
        *(uint32_t*)(d + j) = packh(v.x, v.y);
    }
}

__global__ void tsplit4_kernel(const float* __restrict__ W0, const float* __restrict__ W1,
                               const float* __restrict__ W2, const float* __restrict__ W3,
                               __half* __restrict__ t16) {
    __shared__ float t[32][33];
    const int z = blockIdx.z;
    const float* W = (z == 0) ? W0 : (z == 1) ? W1 : (z == 2) ? W2 : W3;
    const size_t WSZ = (size_t)D_MODEL * D_MODEL;
    __half* tz = t16 + z * WSZ;
    int n0 = blockIdx.x * 32, k0 = blockIdx.y * 32;
    int x = threadIdx.x, y = threadIdx.y;
    #pragma unroll
    for (int j = 0; j < 32; j += 8)
        t[y + j][x] = W[(size_t)(k0 + y + j) * D_MODEL + n0 + x];
    __syncthreads();
    #pragma unroll
    for (int j = 0; j < 32; j += 8)
        tz[(size_t)(n0 + y + j) * D_MODEL + k0 + x] = __float2half(t[x][y + j]);
}

// ---------------------------------------------------------------------------
// GEMM mainloop: fp16 A/B, fp32 accum, BK=64, 3-stage cp.async pipeline
// rows padded to 72 elems (144 B) -> conflict-free ldmatrix
// ---------------------------------------------------------------------------
#define GROWE 72u
#define GABYTES (128u * GROWE * 2u)   // 18432 per array tile (128 x 64 fp16)
#define GSTAGEB (2u * GABYTES)        // A + B = 36864
#define SMEM_GEMM (3u * GSTAGEB)      // 110592

__device__ __forceinline__ void issue_stage(
    uint32_t su, int stage, int k0, int tid, int bm, int bn,
    const __half* __restrict__ A, const __half* __restrict__ B)
{
    uint32_t sb = su + (uint32_t)stage * GSTAGEB;
    #pragma unroll
    for (int j = 0; j < 4; j++) {
        int idx = tid + j * 256;           // 0..1023
        int r = idx >> 3, cu = idx & 7;    // r 0..127, cu 0..7 (16B units)
        uint32_t so = (uint32_t)r * (GROWE * 2u) + (uint32_t)cu * 16u;
        cpa16(sb + 0u * GABYTES + so, A + (size_t)(bm + r) * D_MODEL + k0 + cu * 8);
        cpa16(sb + 1u * GABYTES + so, B + (size_t)(bn + r) * D_MODEL + k0 + cu * 8);
    }
    CP_COMMIT();
}

__device__ __forceinline__ void gemm_core(
    uint32_t su, int tid, int bm, int bn,
    const __half* __restrict__ A, const __half* __restrict__ B,
    float acc[4][4][4])
{
    const int lane = tid & 31, wid = tid >> 5;
    const int wm = (wid >> 2) * 64, wn = (wid & 3) * 32;

    const int NKT = D_MODEL / 64;   // 16
    issue_stage(su, 0, 0, tid, bm, bn, A, B);
    issue_stage(su, 1, 64, tid, bm, bn, A, B);
    issue_stage(su, 2, 128, tid, bm, bn, A, B);

    int slot = 0;
    for (int kt = 0; kt < NKT; kt++) {
        if (kt <= NKT - 3)      CP_WAIT2();
        else if (kt == NKT - 2) CP_WAIT1();
        else                    CP_WAIT0();
        __syncthreads();
        uint32_t sb = su + (uint32_t)slot * GSTAGEB;

        #pragma unroll
        for (int ks = 0; ks < 64; ks += 16) {
            uint32_t a_f[4][4], b_f[2][4];
            #pragma unroll
            for (int mt = 0; mt < 4; mt++) {
                uint32_t off = (uint32_t)((wm + mt * 16 + (lane & 15)) * GROWE
                                          + ks + ((lane >> 4) << 3)) * 2;
                LDMX4(a_f[mt], sb + 0u * GABYTES + off);
            }
            #pragma unroll
            for (int p = 0; p < 2; p++) {
                int rb = wn + p * 16 + (lane & 7) + ((lane >> 4) << 3);
                int ce = ks + (((lane >> 3) & 1) << 3);
                uint32_t off = (uint32_t)(rb * GROWE + ce) * 2;
                LDMX4(b_f[p], sb + 1u * GABYTES + off);
            }
            #pragma unroll
            for (int mt = 0; mt < 4; mt++)
                #pragma unroll
                for (int nt = 0; nt < 4; nt++) {
                    int p = nt >> 1, q = (nt & 1) * 2;
                    mma16816h(acc[mt][nt], a_f[mt], b_f[p][q], b_f[p][q + 1]);
                }
        }
        __syncthreads();
        if (kt + 3 < NKT)
            issue_stage(su, slot, (kt + 3) * 64, tid, bm, bn, A, B);
        slot = (slot == 2) ? 0 : slot + 1;
    }
}

// ---------------------------------------------------------------------------
// Fused QKV projection: outputs fp16, Q pre-scaled.
// ---------------------------------------------------------------------------
__global__ __launch_bounds__(256) void gemm_qkv(
    const __half* __restrict__ x16, const __half* __restrict__ w16,
    const float* __restrict__ bq, const float* __restrict__ bk,
    const float* __restrict__ bv,
    __half* __restrict__ q16, __half* __restrict__ k16, __half* __restrict__ v16)
{
    extern __shared__ char smraw[];
    const uint32_t su = smem_u32(smraw);
    const int tid = threadIdx.x, lane = tid & 31, wid = tid >> 5;
    const int wsel = blockIdx.x >> 3;
    const int bn = (blockIdx.x & 7) * 128, bm = blockIdx.y * 128;
    const size_t WSZ = (size_t)D_MODEL * D_MODEL;

    const __half* B = w16 + (size_t)wsel * WSZ;
    const float* bias = (wsel == 0) ? bq : (wsel == 1) ? bk : bv;
    __half* C = (wsel == 0) ? q16 : (wsel == 1) ? k16 : v16;
    const float scale = (wsel == 0) ? QSCALE : 1.0f;

    float acc[4][4][4];
    #pragma unroll
    for (int i = 0; i < 4; i++)
        #pragma unroll
        for (int j = 0; j < 4; j++)
            #pragma unroll
            for (int q = 0; q < 4; q++) acc[i][j][q] = 0.0f;

    gemm_core(su, tid, bm, bn, x16, B, acc);

    const int wm = (wid >> 2) * 64, wn = (wid & 3) * 32;
    #pragma unroll
    for (int mt = 0; mt < 4; mt++) {
        int m0 = bm + wm + mt * 16 + (lane >> 2);
        #pragma unroll
        for (int nt = 0; nt < 4; nt++) {
            int n = bn + wn + nt * 8 + (lane & 3) * 2;
            float bx = bias[n], by = bias[n + 1];
            float v0 = (acc[mt][nt][0] + bx) * scale;
            float v1 = (acc[mt][nt][1] + by) * scale;
            float v2 = (acc[mt][nt][2] + bx) * scale;
            float v3 = (acc[mt][nt][3] + by) * scale;
            #pragma unroll
            for (int rr = 0; rr < 2; rr++) {
                int m = m0 + rr * 8;
                float a = rr ? v2 : v0, b = rr ? v3 : v1;
                int bb = m >> 11, ss = m & 2047, hh = n >> 6, dd = n & 63;
                size_t o = (((size_t)(bb * NHEADS + hh) * SEQ + ss) * HD + dd);
                *(uint32_t*)(C + o) = packh(a, b);
            }
        }
    }
}

// ---------------------------------------------------------------------------
// Output projection: fp32 flat out
// ---------------------------------------------------------------------------
__global__ __launch_bounds__(256) void gemm_o(
    const __half* __restrict__ ct16, const __half* __restrict__ Bw,
    const float* __restrict__ bias, float* __restrict__ Cf)
{
    extern __shared__ char smraw[];
    const uint32_t su = smem_u32(smraw);
    const int tid = threadIdx.x, lane = tid & 31, wid = tid >> 5;
    const int bn = blockIdx.x * 128, bm = blockIdx.y * 128;

    float acc[4][4][4];
    #pragma unroll
    for (int i = 0; i < 4; i++)
        #pragma unroll
        for (int j = 0; j < 4; j++)
            #pragma unroll
            for (int q = 0; q < 4; q++) acc[i][j][q] = 0.0f;

    gemm_core(su, tid, bm, bn, ct16, Bw, acc);

    const int wm = (wid >> 2) * 64, wn = (wid & 3) * 32;
    #pragma unroll
    for (int mt = 0; mt < 4; mt++) {
        int m0 = bm + wm + mt * 16 + (lane >> 2);
        #pragma unroll
        for (int nt = 0; nt < 4; nt++) {
            int n = bn + wn + nt * 8 + (lane & 3) * 2;
            float bx = bias[n], by = bias[n + 1];
            *(float2*)(Cf + (size_t)m0 * D_MODEL + n) =
                make_float2(acc[mt][nt][0] + bx, acc[mt][nt][1] + by);
            *(float2*)(Cf + (size_t)(m0 + 8) * D_MODEL + n) =
                make_float2(acc[mt][nt][2] + bx, acc[mt][nt][3] + by);
        }
    }
}

// ---------------------------------------------------------------------------
// FA2 mma attention, fp16 operands, 3-stage KV pipeline.
// __launch_bounds__(256, 3): target <=85 regs -> 3 CTAs/SM (24 warps).
// ---------------------------------------------------------------------------
#define ROWB 144u
#define Q_BYTES (128u * ROWB)
#define KV_ARR (64u * ROWB)
#define KV_STAGE (2u * KV_ARR)                   // K, V
#define SMEM_ATTN (Q_BYTES + 3u * KV_STAGE)      // 73728

__device__ __forceinline__ void attn_issue_kv(
    uint32_t sb, const __half* __restrict__ k16, const __half* __restrict__ v16,
    size_t gbase, int j0, int tid)
{
    #pragma unroll
    for (int i = 0; i < 2; i++) {
        int c = tid + i * 256;
        int r = c >> 3, u = c & 7;
        uint32_t so = (uint32_t)r * ROWB + (uint32_t)u * 16u;
        size_t go = gbase + (size_t)(j0 + r) * HD + u * 8;
        cpa16(sb + 0u * KV_ARR + so, k16 + go);
        cpa16(sb + 1u * KV_ARR + so, v16 + go);
    }
    CP_COMMIT();
}

__global__ __launch_bounds__(256, 3) void attn_mma(
    const __half* __restrict__ q16, const __half* __restrict__ k16,
    const __half* __restrict__ v16, __half* __restrict__ ct16)
{
    extern __shared__ char smraw[];
    const uint32_t su = smem_u32(smraw);
    const uint32_t Q_s = su;
    const uint32_t KV0 = su + Q_BYTES;

    const int qt = (gridDim.x - 1) - blockIdx.x;
    const int h = blockIdx.y, b = blockIdx.z;
    const int bh = b * NHEADS + h;
    const size_t gbase = (size_t)bh * SEQ * HD;
    const int q0 = qt * 128;
    const int ntiles = 2 * qt + 2;

    const int tid = threadIdx.x, lane = tid & 31, wid = tid >> 5;
    const int wm = wid * 16;
    const int qr = q0 + wm;

    // Q load joins commit group 0
    #pragma unroll
    for (int i = 0; i < 4; i++) {
        int c = tid + i * 256;
        int r = c >> 3, u = c & 7;
        uint32_t so = (uint32_t)r * ROWB + (uint32_t)u * 16u;
        cpa16(Q_s + so, q16 + gbase + (size_t)(q0 + r) * HD + u * 8);
    }
    attn_issue_kv(KV0, k16, v16, gbase, 0, tid);
    if (ntiles > 1) attn_issue_kv(KV0 + KV_STAGE, k16, v16, gbase, 64, tid);
    if (ntiles > 2) attn_issue_kv(KV0 + 2u * KV_STAGE, k16, v16, gbase, 128, tid);

    float o[8][4];
    #pragma unroll
    for (int nt = 0; nt < 8; nt++)
        #pragma unroll
        for (int q = 0; q < 4; q++) o[nt][q] = 0.0f;
    float m0 = -1e30f, m1 = -1e30f, l0 = 0.0f, l1 = 0.0f;

    int slot = 0;
    for (int t = 0; t < ntiles; t++) {
        if (t <= ntiles - 3)      CP_WAIT2();
        else if (t == ntiles - 2) CP_WAIT1();
        else                      CP_WAIT0();
        __syncthreads();
        const int j0 = t * 64;
        const uint32_t sb = KV0 + (uint32_t)slot * KV_STAGE;
        const uint32_t k_s = sb, v_s = sb + KV_ARR;

        // ---- S = Q K^T (log2 domain) ----
        float s[8][4];
        #pragma unroll
        for (int nt = 0; nt < 8; nt++)
            #pragma unroll
            for (int q = 0; q < 4; q++) s[nt][q] = 0.0f;

        #pragma unroll
        for (int ks = 0; ks < 4; ks++) {
            uint32_t ah[4];
            {
                uint32_t off = (uint32_t)(wm + (lane & 15)) * ROWB
                             + (uint32_t)(ks * 16 + ((lane >> 4) << 3)) * 2u;
                LDMX4(ah, Q_s + off);
            }
            #pragma unroll
            for (int np = 0; np < 4; np++) {
                int rk = np * 16 + ((lane >> 4) << 3) + (lane & 7);
                uint32_t off = (uint32_t)rk * ROWB
                             + (uint32_t)(ks * 16 + (((lane >> 3) & 1) << 3)) * 2u;
                uint32_t kf[4];
                LDMX4(kf, k_s + off);
                #pragma unroll
                for (int q2 = 0; q2 < 2; q2++)
                    mma16816h(s[np * 2 + q2], ah, kf[q2 * 2], kf[q2 * 2 + 1]);
            }
        }

        // ---- causal mask ----
        if (j0 + 63 > qr) {
            int r0 = qr + (lane >> 2), r1 = r0 + 8;
            #pragma unroll
            for (int nt = 0; nt < 8; nt++)
                #pragma unroll
                for (int c = 0; c < 2; c++) {
                    int k = j0 + nt * 8 + (lane & 3) * 2 + c;
                    if (k > r0) s[nt][c] = -1e30f;
                    if (k > r1) s[nt][2 + c] = -1e30f;
                }
        }

        // ---- row max + rescale ----
        float mx0 = -1e30f, mx1 = -1e30f;
        #pragma unroll
        for (int nt = 0; nt < 8; nt++) {
            mx0 = fmaxf(mx0, fmaxf(s[nt][0], s[nt][1]));
            mx1 = fmaxf(mx1, fmaxf(s[nt][2], s[nt][3]));
        }
        mx0 = fmaxf(mx0, __shfl_xor_sync(0xffffffffu, mx0, 1));
        mx0 = fmaxf(mx0, __shfl_xor_sync(0xffffffffu, mx0, 2));
        mx1 = fmaxf(mx1, __shfl_xor_sync(0xffffffffu, mx1, 1));
        mx1 = fmaxf(mx1, __shfl_xor_sync(0xffffffffu, mx1, 2));
        float mn0 = fmaxf(m0, mx0), mn1 = fmaxf(m1, mx1);
        float c0 = ex2f(m0 - mn0), c1 = ex2f(m1 - mn1);
        m0 = mn0; m1 = mn1;
        #pragma unroll
        for (int nt = 0; nt < 8; nt++) {
            o[nt][0] *= c0; o[nt][1] *= c0;
            o[nt][2] *= c1; o[nt][3] *= c1;
        }
        float sum0 = 0.0f, sum1 = 0.0f;

        // ---- interleaved exp + P pack + PV mma ----
        #pragma unroll
        for (int kb = 0; kb < 4; kb++) {
            uint32_t Ap[4];
            #pragma unroll
            for (int half = 0; half < 2; half++) {
                int nt = kb * 2 + half;
                float p0 = ex2f(s[nt][0] - mn0);
                float p1 = ex2f(s[nt][1] - mn0);
                float p2 = ex2f(s[nt][2] - mn1);
                float p3 = ex2f(s[nt][3] - mn1);
                sum0 += p0 + p1;
                sum1 += p2 + p3;
                Ap[half * 2 + 0] = packh(p0, p1);
                Ap[half * 2 + 1] = packh(p2, p3);
            }
            #pragma unroll
            for (int np = 0; np < 4; np++) {
                int rv = kb * 16 + (((lane >> 3) & 1) << 3) + (lane & 7);
                int cv = np * 16 + ((lane >> 4) << 3);
                uint32_t off = (uint32_t)rv * ROWB + (uint32_t)cv * 2u;
                uint32_t vf[4];
                LDMX4T(vf, v_s + off);
                #pragma unroll
                for (int q2 = 0; q2 < 2; q2++)
                    mma16816h(o[np * 2 + q2], Ap, vf[q2 * 2], vf[q2 * 2 + 1]);
            }
        }

        sum0 += __shfl_xor_sync(0xffffffffu, sum0, 1);
        sum0 += __shfl_xor_sync(0xffffffffu, sum0, 2);
        sum1 += __shfl_xor_sync(0xffffffffu, sum1, 1);
        sum1 += __shfl_xor_sync(0xffffffffu, sum1, 2);
        l0 = l0 * c0 + sum0;
        l1 = l1 * c1 + sum1;

        __syncthreads();
        if (t + 3 < ntiles)
            attn_issue_kv(KV0 + (uint32_t)slot * KV_STAGE, k16, v16,
                          gbase, (t + 3) * 64, tid);
        slot = (slot == 2) ? 0 : slot + 1;
    }

    // ---- epilogue ----
    float inv0 = 1.0f / l0, inv1 = 1.0f / l1;
    int r0 = qr + (lane >> 2);
    size_t tok0 = (size_t)(b * SEQ + r0) * D_MODEL + h * HD;
    size_t tok1 = tok0 + 8 * D_MODEL;
    #pragma unroll
    for (int nt = 0; nt < 8; nt++) {
        int col = nt * 8 + (lane & 3) * 2;
        *(uint32_t*)(ct16 + tok0 + col) = packh(o[nt][0] * inv0, o[nt][1] * inv0);
        *(uint32_t*)(ct16 + tok1 + col) = packh(o[nt][2] * inv1, o[nt][3] * inv1);
    }
}

// ---------------------------------------------------------------------------
extern "C" void kernel_launch(void* const* d_in, const int* in_sizes, int n_in,
                              void* d_out, int out_size)
{
    const float* x  = (const float*)d_in[0];
    const float* Wq = (const float*)d_in[1];
    const float* bq = (const float*)d_in[2];
    const float* Wk = (const float*)d_in[3];
    const float* bk = (const float*)d_in[4];
    const float* Wv = (const float*)d_in[5];
    const float* bv = (const float*)d_in[6];
    const float* Wo = (const float*)d_in[7];
    const float* bo = (const float*)d_in[8];
    float* out = (float*)d_out;

    __half *x16, *qp, *kp, *vp, *ct16, *w16;
    cudaGetSymbolAddress((void**)&x16, g_x16);
    cudaGetSymbolAddress((void**)&qp, g_q16);
    cudaGetSymbolAddress((void**)&kp, g_k16);
    cudaGetSymbolAddress((void**)&vp, g_v16);
    cudaGetSymbolAddress((void**)&ct16, g_ct16);
    cudaGetSymbolAddress((void**)&w16, g_w16);

    const size_t WSZ = (size_t)D_MODEL * D_MODEL;

    cvt16_kernel<<<1024, 256>>>(x, x16, NTOK * D_MODEL);
    dim3 tg(32, 32, 4), tb(32, 8);
    tsplit4_kernel<<<tg, tb>>>(Wq, Wk, Wv, Wo, w16);

    cudaFuncSetAttribute(gemm_qkv, cudaFuncAttributeMaxDynamicSharedMemorySize, SMEM_GEMM);
    cudaFuncSetAttribute(gemm_o, cudaFuncAttributeMaxDynamicSharedMemorySize, SMEM_GEMM);

    dim3 gqkv(24, NTOK / 128);
    gemm_qkv<<<gqkv, 256, SMEM_GEMM>>>(x16, w16, bq, bk, bv, qp, kp, vp);

    cudaFuncSetAttribute(attn_mma, cudaFuncAttributeMaxDynamicSharedMemorySize, SMEM_ATTN);
    dim3 ga(SEQ / 128, NHEADS, BATCH);
    attn_mma<<<ga, 256, SMEM_ATTN>>>(qp, kp, vp, ct16);

    gemm_o<<<dim3(D_MODEL / 128, NTOK / 128), 256, SMEM_GEMM>>>(
        ct16, w16 + 3 * WSZ, bo, out);
}

// round 16
// speedup vs baseline: 1.1226x; 1.1226x over previous
#include <cuda_runtime.h>
#include <cuda_fp16.h>
#include <cstdint>
#include <math.h>

#define D_MODEL 1024
#define NHEADS 16
#define HD 64
#define BATCH 2
#define SEQ 2048
#define NTOK (BATCH * SEQ)   // 4096

// Q pre-scale: (1/sqrt(64)) * log2(e)  -> scores in log2 domain
#define QSCALE 0.180336875967866f

// ---------------------------------------------------------------------------
// Scratch (no allocations allowed)
// ---------------------------------------------------------------------------
__device__ __half g_x16[(size_t)NTOK * D_MODEL];
__device__ __half g_q16[(size_t)NTOK * D_MODEL];   // [B,H,S,hd] fp16, scaled
__device__ __half g_k16[(size_t)NTOK * D_MODEL];
__device__ __half g_v16[(size_t)NTOK * D_MODEL];
__device__ __half g_ct16[(size_t)NTOK * D_MODEL];  // ctx fp16 flat
__device__ __half g_w16[(size_t)4 * D_MODEL * D_MODEL];  // [n][k] fp16

// ---------------------------------------------------------------------------
// Helpers
// ---------------------------------------------------------------------------
__device__ __forceinline__ uint32_t smem_u32(const void* p) {
    uint32_t a;
    asm("{ .reg .u64 t; cvta.to.shared.u64 t, %1; cvt.u32.u64 %0, t; }" : "=r"(a) : "l"(p));
    return a;
}
__device__ __forceinline__ void cpa16(uint32_t s, const void* g) {
    asm volatile("cp.async.cg.shared.global [%0], [%1], 16;" :: "r"(s), "l"(g));
}
#define CP_COMMIT() asm volatile("cp.async.commit_group;" ::: "memory")
#define CP_WAIT2()  asm volatile("cp.async.wait_group 2;" ::: "memory")
#define CP_WAIT1()  asm volatile("cp.async.wait_group 1;" ::: "memory")
#define CP_WAIT0()  asm volatile("cp.async.wait_group 0;" ::: "memory")

#define LDMX4(r, a) \
    asm volatile("ldmatrix.sync.aligned.m8n8.x4.shared.b16 {%0,%1,%2,%3}, [%4];" \
        : "=r"((r)[0]), "=r"((r)[1]), "=r"((r)[2]), "=r"((r)[3]) : "r"(a))
#define LDMX4T(r, a) \
    asm volatile("ldmatrix.sync.aligned.m8n8.x4.trans.shared.b16 {%0,%1,%2,%3}, [%4];" \
        : "=r"((r)[0]), "=r"((r)[1]), "=r"((r)[2]), "=r"((r)[3]) : "r"(a))

__device__ __forceinline__ void mma16816h(float* c, const uint32_t* a, uint32_t b0, uint32_t b1) {
    asm volatile(
        "mma.sync.aligned.m16n8k16.row.col.f32.f16.f16.f32 "
        "{%0,%1,%2,%3}, {%4,%5,%6,%7}, {%8,%9}, {%0,%1,%2,%3};"
        : "+f"(c[0]), "+f"(c[1]), "+f"(c[2]), "+f"(c[3])
        : "r"(a[0]), "r"(a[1]), "r"(a[2]), "r"(a[3]), "r"(b0), "r"(b1));
}

__device__ __forceinline__ uint32_t packh(float lo, float hi) {
    uint32_t r;
    asm("cvt.rn.f16x2.f32 %0, %1, %2;" : "=r"(r) : "f"(hi), "f"(lo));
    return r;
}
__device__ __forceinline__ float ex2f(float x) {
    float y;
    asm("ex2.approx.f32 %0, %1;" : "=f"(y) : "f"(x));
    return y;
}

// ---------------------------------------------------------------------------
// Fused prep: z=0..3 -> weight [k][n] fp32 -> [n][k] fp16; z=4 -> x fp32->fp16
// ---------------------------------------------------------------------------
__global__ void prep_kernel(const float* __restrict__ W0, const float* __restrict__ W1,
                            const float* __restrict__ W2, const float* __restrict__ W3,
                            const float* __restrict__ x, __half* __restrict__ t16,
                            __half* __restrict__ x16) {
    const int z = blockIdx.z;
    if (z == 4) {
        // x conversion: 1024 blocks x 256 threads, 4096 elems per block
        int blk = blockIdx.y * 32 + blockIdx.x;
        int base = blk * 4096 + (threadIdx.y * 32 + threadIdx.x) * 2;
        #pragma unroll
        for (int i = 0; i < 8; i++) {
            int j = base + i * 512;
            float2 v = *(const float2*)(x + j);
            *(uint32_t*)(x16 + j) = packh(v.x, v.y);
        }
        return;
    }
    __shared__ float t[32][33];
    const float* W = (z == 0) ? W0 : (z == 1) ? W1 : (z == 2) ? W2 : W3;
    const size_t WSZ = (size_t)D_MODEL * D_MODEL;
    __half* tz = t16 + z * WSZ;
    int n0 = blockIdx.x * 32, k0 = blockIdx.y * 32;
    int xx = threadIdx.x, yy = threadIdx.y;
    #pragma unroll
    for (int j = 0; j < 32; j += 8)
        t[yy + j][xx] = W[(size_t)(k0 + yy + j) * D_MODEL + n0 + xx];
    __syncthreads();
    #pragma unroll
    for (int j = 0; j < 32; j += 8)
        tz[(size_t)(n0 + yy + j) * D_MODEL + k0 + xx] = __float2half(t[xx][yy + j]);
}

// ---------------------------------------------------------------------------
// GEMM mainloop: fp16 A/B, fp32 accum, BK=64, 2-stage cp.async pipeline
// rows padded to 72 elems (144 B) -> conflict-free ldmatrix
// ---------------------------------------------------------------------------
#define GROWE 72u
#define GABYTES (128u * GROWE * 2u)   // 18432 per array tile (128 x 64 fp16)
#define GSTAGEB (2u * GABYTES)        // A + B = 36864
#define SMEM_GEMM (2u * GSTAGEB)      // 73728

__device__ __forceinline__ void issue_stage(
    uint32_t su, int stage, int k0, int tid, int bm, int bn,
    const __half* __restrict__ A, const __half* __restrict__ B)
{
    uint32_t sb = su + (uint32_t)stage * GSTAGEB;
    #pragma unroll
    for (int j = 0; j < 4; j++) {
        int idx = tid + j * 256;           // 0..1023
        int r = idx >> 3, cu = idx & 7;    // r 0..127, cu 0..7 (16B units)
        uint32_t so = (uint32_t)r * (GROWE * 2u) + (uint32_t)cu * 16u;
        cpa16(sb + 0u * GABYTES + so, A + (size_t)(bm + r) * D_MODEL + k0 + cu * 8);
        cpa16(sb + 1u * GABYTES + so, B + (size_t)(bn + r) * D_MODEL + k0 + cu * 8);
    }
    CP_COMMIT();
}

__device__ __forceinline__ void gemm_core(
    uint32_t su, int tid, int bm, int bn,
    const __half* __restrict__ A, const __half* __restrict__ B,
    float acc[4][4][4])
{
    const int lane = tid & 31, wid = tid >> 5;
    const int wm = (wid >> 2) * 64, wn = (wid & 3) * 32;

    issue_stage(su, 0, 0, tid, bm, bn, A, B);

    const int NKT = D_MODEL / 64;   // 16
    for (int kt = 0; kt < NKT; kt++) {
        if (kt + 1 < NKT) {
            issue_stage(su, (kt + 1) & 1, (kt + 1) * 64, tid, bm, bn, A, B);
            CP_WAIT1();
        } else {
            CP_WAIT0();
        }
        __syncthreads();
        uint32_t sb = su + (uint32_t)(kt & 1) * GSTAGEB;

        #pragma unroll
        for (int ks = 0; ks < 64; ks += 16) {
            uint32_t a_f[4][4], b_f[2][4];
            #pragma unroll
            for (int mt = 0; mt < 4; mt++) {
                uint32_t off = (uint32_t)((wm + mt * 16 + (lane & 15)) * GROWE
                                          + ks + ((lane >> 4) << 3)) * 2;
                LDMX4(a_f[mt], sb + 0u * GABYTES + off);
            }
            #pragma unroll
            for (int p = 0; p < 2; p++) {
                int rb = wn + p * 16 + (lane & 7) + ((lane >> 4) << 3);
                int ce = ks + (((lane >> 3) & 1) << 3);
                uint32_t off = (uint32_t)(rb * GROWE + ce) * 2;
                LDMX4(b_f[p], sb + 1u * GABYTES + off);
            }
            #pragma unroll
            for (int mt = 0; mt < 4; mt++)
                #pragma unroll
                for (int nt = 0; nt < 4; nt++) {
                    int p = nt >> 1, q = (nt & 1) * 2;
                    mma16816h(acc[mt][nt], a_f[mt], b_f[p][q], b_f[p][q + 1]);
                }
        }
        __syncthreads();
    }
}

// ---------------------------------------------------------------------------
// Fused QKV projection: outputs fp16, Q pre-scaled.
// ---------------------------------------------------------------------------
__global__ __launch_bounds__(256) void gemm_qkv(
    const __half* __restrict__ x16, const __half* __restrict__ w16,
    const float* __restrict__ bq, const float* __restrict__ bk,
    const float* __restrict__ bv,
    __half* __restrict__ q16, __half* __restrict__ k16, __half* __restrict__ v16)
{
    extern __shared__ char smraw[];
    const uint32_t su = smem_u32(smraw);
    const int tid = threadIdx.x, lane = tid & 31, wid = tid >> 5;
    const int wsel = blockIdx.x >> 3;
    const int bn = (blockIdx.x & 7) * 128, bm = blockIdx.y * 128;
    const size_t WSZ = (size_t)D_MODEL * D_MODEL;

    const __half* B = w16 + (size_t)wsel * WSZ;
    const float* bias = (wsel == 0) ? bq : (wsel == 1) ? bk : bv;
    __half* C = (wsel == 0) ? q16 : (wsel == 1) ? k16 : v16;
    const float scale = (wsel == 0) ? QSCALE : 1.0f;

    float acc[4][4][4];
    #pragma unroll
    for (int i = 0; i < 4; i++)
        #pragma unroll
        for (int j = 0; j < 4; j++)
            #pragma unroll
            for (int q = 0; q < 4; q++) acc[i][j][q] = 0.0f;

    gemm_core(su, tid, bm, bn, x16, B, acc);

    const int wm = (wid >> 2) * 64, wn = (wid & 3) * 32;
    #pragma unroll
    for (int mt = 0; mt < 4; mt++) {
        int m0 = bm + wm + mt * 16 + (lane >> 2);
        #pragma unroll
        for (int nt = 0; nt < 4; nt++) {
            int n = bn + wn + nt * 8 + (lane & 3) * 2;
            float bx = bias[n], by = bias[n + 1];
            float v0 = (acc[mt][nt][0] + bx) * scale;
            float v1 = (acc[mt][nt][1] + by) * scale;
            float v2 = (acc[mt][nt][2] + bx) * scale;
            float v3 = (acc[mt][nt][3] + by) * scale;
            #pragma unroll
            for (int rr = 0; rr < 2; rr++) {
                int m = m0 + rr * 8;
                float a = rr ? v2 : v0, b = rr ? v3 : v1;
                int bb = m >> 11, ss = m & 2047, hh = n >> 6, dd = n & 63;
                size_t o = (((size_t)(bb * NHEADS + hh) * SEQ + ss) * HD + dd);
                *(uint32_t*)(C + o) = packh(a, b);
            }
        }
    }
}

// ---------------------------------------------------------------------------
// Output projection: fp32 flat out
// ---------------------------------------------------------------------------
__global__ __launch_bounds__(256) void gemm_o(
    const __half* __restrict__ ct16, const __half* __restrict__ Bw,
    const float* __restrict__ bias, float* __restrict__ Cf)
{
    extern __shared__ char smraw[];
    const uint32_t su = smem_u32(smraw);
    const int tid = threadIdx.x, lane = tid & 31, wid = tid >> 5;
    const int bn = blockIdx.x * 128, bm = blockIdx.y * 128;

    float acc[4][4][4];
    #pragma unroll
    for (int i = 0; i < 4; i++)
        #pragma unroll
        for (int j = 0; j < 4; j++)
            #pragma unroll
            for (int q = 0; q < 4; q++) acc[i][j][q] = 0.0f;

    gemm_core(su, tid, bm, bn, ct16, Bw, acc);

    const int wm = (wid >> 2) * 64, wn = (wid & 3) * 32;
    #pragma unroll
    for (int mt = 0; mt < 4; mt++) {
        int m0 = bm + wm + mt * 16 + (lane >> 2);
        #pragma unroll
        for (int nt = 0; nt < 4; nt++) {
            int n = bn + wn + nt * 8 + (lane & 3) * 2;
            float bx = bias[n], by = bias[n + 1];
            *(float2*)(Cf + (size_t)m0 * D_MODEL + n) =
                make_float2(acc[mt][nt][0] + bx, acc[mt][nt][1] + by);
            *(float2*)(Cf + (size_t)(m0 + 8) * D_MODEL + n) =
                make_float2(acc[mt][nt][2] + bx, acc[mt][nt][3] + by);
        }
    }
}

// ---------------------------------------------------------------------------
// FA2 mma attention, fp16 operands, 3-stage KV pipeline.
// Q fragments hoisted into registers (loaded once at t=0).
// ---------------------------------------------------------------------------
#define ROWB 144u
#define Q_BYTES (128u * ROWB)
#define KV_ARR (64u * ROWB)
#define KV_STAGE (2u * KV_ARR)                   // K, V
#define SMEM_ATTN (Q_BYTES + 3u * KV_STAGE)      // 73728

__device__ __forceinline__ void attn_issue_kv(
    uint32_t sb, const __half* __restrict__ k16, const __half* __restrict__ v16,
    size_t gbase, int j0, int tid)
{
    #pragma unroll
    for (int i = 0; i < 2; i++) {
        int c = tid + i * 256;
        int r = c >> 3, u = c & 7;
        uint32_t so = (uint32_t)r * ROWB + (uint32_t)u * 16u;
        size_t go = gbase + (size_t)(j0 + r) * HD + u * 8;
        cpa16(sb + 0u * KV_ARR + so, k16 + go);
        cpa16(sb + 1u * KV_ARR + so, v16 + go);
    }
    CP_COMMIT();
}

__global__ __launch_bounds__(256) void attn_mma(
    const __half* __restrict__ q16, const __half* __restrict__ k16,
    const __half* __restrict__ v16, __half* __restrict__ ct16)
{
    extern __shared__ char smraw[];
    const uint32_t su = smem_u32(smraw);
    const uint32_t Q_s = su;
    const uint32_t KV0 = su + Q_BYTES;

    const int qt = (gridDim.x - 1) - blockIdx.x;
    const int h = blockIdx.y, b = blockIdx.z;
    const int bh = b * NHEADS + h;
    const size_t gbase = (size_t)bh * SEQ * HD;
    const int q0 = qt * 128;
    const int ntiles = 2 * qt + 2;

    const int tid = threadIdx.x, lane = tid & 31, wid = tid >> 5;
    const int wm = wid * 16;
    const int qr = q0 + wm;

    // Q load joins commit group 0
    #pragma unroll
    for (int i = 0; i < 4; i++) {
        int c = tid + i * 256;
        int r = c >> 3, u = c & 7;
        uint32_t so = (uint32_t)r * ROWB + (uint32_t)u * 16u;
        cpa16(Q_s + so, q16 + gbase + (size_t)(q0 + r) * HD + u * 8);
    }
    attn_issue_kv(KV0, k16, v16, gbase, 0, tid);
    if (ntiles > 1) attn_issue_kv(KV0 + KV_STAGE, k16, v16, gbase, 64, tid);
    if (ntiles > 2) attn_issue_kv(KV0 + 2u * KV_STAGE, k16, v16, gbase, 128, tid);

    float o[8][4];
    #pragma unroll
    for (int nt = 0; nt < 8; nt++)
        #pragma unroll
        for (int q = 0; q < 4; q++) o[nt][q] = 0.0f;
    float m0 = -1e30f, m1 = -1e30f, l0 = 0.0f, l1 = 0.0f;

    uint32_t aq[4][4];   // hoisted Q fragments (16 regs), loaded at t=0

    int slot = 0;
    for (int t = 0; t < ntiles; t++) {
        if (t <= ntiles - 3)      CP_WAIT2();
        else if (t == ntiles - 2) CP_WAIT1();
        else                      CP_WAIT0();
        __syncthreads();

        if (t == 0) {
            #pragma unroll
            for (int ks = 0; ks < 4; ks++) {
                uint32_t off = (uint32_t)(wm + (lane & 15)) * ROWB
                             + (uint32_t)(ks * 16 + ((lane >> 4) << 3)) * 2u;
                LDMX4(aq[ks], Q_s + off);
            }
        }

        const int j0 = t * 64;
        const uint32_t sb = KV0 + (uint32_t)slot * KV_STAGE;
        const uint32_t k_s = sb, v_s = sb + KV_ARR;

        // ---- S = Q K^T (log2 domain) ----
        float s[8][4];
        #pragma unroll
        for (int nt = 0; nt < 8; nt++)
            #pragma unroll
            for (int q = 0; q < 4; q++) s[nt][q] = 0.0f;

        #pragma unroll
        for (int ks = 0; ks < 4; ks++) {
            #pragma unroll
            for (int np = 0; np < 4; np++) {
                int rk = np * 16 + ((lane >> 4) << 3) + (lane & 7);
                uint32_t off = (uint32_t)rk * ROWB
                             + (uint32_t)(ks * 16 + (((lane >> 3) & 1) << 3)) * 2u;
                uint32_t kf[4];
                LDMX4(kf, k_s + off);
                #pragma unroll
                for (int q2 = 0; q2 < 2; q2++)
                    mma16816h(s[np * 2 + q2], aq[ks], kf[q2 * 2], kf[q2 * 2 + 1]);
            }
        }

        // ---- causal mask ----
        if (j0 + 63 > qr) {
            int r0 = qr + (lane >> 2), r1 = r0 + 8;
            #pragma unroll
            for (int nt = 0; nt < 8; nt++)
                #pragma unroll
                for (int c = 0; c < 2; c++) {
                    int k = j0 + nt * 8 + (lane & 3) * 2 + c;
                    if (k > r0) s[nt][c] = -1e30f;
                    if (k > r1) s[nt][2 + c] = -1e30f;
                }
        }

        // ---- row max + rescale ----
        float mx0 = -1e30f, mx1 = -1e30f;
        #pragma unroll
        for (int nt = 0; nt < 8; nt++) {
            mx0 = fmaxf(mx0, fmaxf(s[nt][0], s[nt][1]));
            mx1 = fmaxf(mx1, fmaxf(s[nt][2], s[nt][3]));
        }
        mx0 = fmaxf(mx0, __shfl_xor_sync(0xffffffffu, mx0, 1));
        mx0 = fmaxf(mx0, __shfl_xor_sync(0xffffffffu, mx0, 2));
        mx1 = fmaxf(mx1, __shfl_xor_sync(0xffffffffu, mx1, 1));
        mx1 = fmaxf(mx1, __shfl_xor_sync(0xffffffffu, mx1, 2));
        float mn0 = fmaxf(m0, mx0), mn1 = fmaxf(m1, mx1);
        float c0 = ex2f(m0 - mn0), c1 = ex2f(m1 - mn1);
        m0 = mn0; m1 = mn1;
        #pragma unroll
        for (int nt = 0; nt < 8; nt++) {
            o[nt][0] *= c0; o[nt][1] *= c0;
            o[nt][2] *= c1; o[nt][3] *= c1;
        }
        float sum0 = 0.0f, sum1 = 0.0f;

        // ---- interleaved exp + P pack + PV mma ----
        #pragma unroll
        for (int kb = 0; kb < 4; kb++) {
            uint32_t Ap[4];
            #pragma unroll
            for (int half = 0; half < 2; half++) {
                int nt = kb * 2 + half;
                float p0 = ex2f(s[nt][0] - mn0);
                float p1 = ex2f(s[nt][1] - mn0);
                float p2 = ex2f(s[nt][2] - mn1);
                float p3 = ex2f(s[nt][3] - mn1);
                sum0 += p0 + p1;
                sum1 += p2 + p3;
                Ap[half * 2 + 0] = packh(p0, p1);
                Ap[half * 2 + 1] = packh(p2, p3);
            }
            #pragma unroll
            for (int np = 0; np < 4; np++) {
                int rv = kb * 16 + (((lane >> 3) & 1) << 3) + (lane & 7);
                int cv = np * 16 + ((lane >> 4) << 3);
                uint32_t off = (uint32_t)rv * ROWB + (uint32_t)cv * 2u;
                uint32_t vf[4];
                LDMX4T(vf, v_s + off);
                #pragma unroll
                for (int q2 = 0; q2 < 2; q2++)
                    mma16816h(o[np * 2 + q2], Ap, vf[q2 * 2], vf[q2 * 2 + 1]);
            }
        }

        sum0 += __shfl_xor_sync(0xffffffffu, sum0, 1);
        sum0 += __shfl_xor_sync(0xffffffffu, sum0, 2);
        sum1 += __shfl_xor_sync(0xffffffffu, sum1, 1);
        sum1 += __shfl_xor_sync(0xffffffffu, sum1, 2);
        l0 = l0 * c0 + sum0;
        l1 = l1 * c1 + sum1;

        __syncthreads();
        if (t + 3 < ntiles)
            attn_issue_kv(KV0 + (uint32_t)slot * KV_STAGE, k16, v16,
                          gbase, (t + 3) * 64, tid);
        slot = (slot == 2) ? 0 : slot + 1;
    }

    // ---- epilogue ----
    float inv0 = 1.0f / l0, inv1 = 1.0f / l1;
    int r0 = qr + (lane >> 2);
    size_t tok0 = (size_t)(b * SEQ + r0) * D_MODEL + h * HD;
    size_t tok1 = tok0 + 8 * D_MODEL;
    #pragma unroll
    for (int nt = 0; nt < 8; nt++) {
        int col = nt * 8 + (lane & 3) * 2;
        *(uint32_t*)(ct16 + tok0 + col) = packh(o[nt][0] * inv0, o[nt][1] * inv0);
        *(uint32_t*)(ct16 + tok1 + col) = packh(o[nt][2] * inv1, o[nt][3] * inv1);
    }
}

// ---------------------------------------------------------------------------
extern "C" void kernel_launch(void* const* d_in, const int* in_sizes, int n_in,
                              void* d_out, int out_size)
{
    const float* x  = (const float*)d_in[0];
    const float* Wq = (const float*)d_in[1];
    const float* bq = (const float*)d_in[2];
    const float* Wk = (const float*)d_in[3];
    const float* bk = (const float*)d_in[4];
    const float* Wv = (const float*)d_in[5];
    const float* bv = (const float*)d_in[6];
    const float* Wo = (const float*)d_in[7];
    const float* bo = (const float*)d_in[8];
    float* out = (float*)d_out;

    __half *x16, *qp, *kp, *vp, *ct16, *w16;
    cudaGetSymbolAddress((void**)&x16, g_x16);
    cudaGetSymbolAddress((void**)&qp, g_q16);
    cudaGetSymbolAddress((void**)&kp, g_k16);
    cudaGetSymbolAddress((void**)&vp, g_v16);
    cudaGetSymbolAddress((void**)&ct16, g_ct16);
    cudaGetSymbolAddress((void**)&w16, g_w16);

    const size_t WSZ = (size_t)D_MODEL * D_MODEL;

    dim3 tg(32, 32, 5), tb(32, 8);
    prep_kernel<<<tg, tb>>>(Wq, Wk, Wv, Wo, x, w16, x16);

    cudaFuncSetAttribute(gemm_qkv, cudaFuncAttributeMaxDynamicSharedMemorySize, SMEM_GEMM);
    cudaFuncSetAttribute(gemm_o, cudaFuncAttributeMaxDynamicSharedMemorySize, SMEM_GEMM);

    dim3 gqkv(24, NTOK / 128);
    gemm_qkv<<<gqkv, 256, SMEM_GEMM>>>(x16, w16, bq, bk, bv, qp, kp, vp);

    cudaFuncSetAttribute(attn_mma, cudaFuncAttributeMaxDynamicSharedMemorySize, SMEM_ATTN);
    dim3 ga(SEQ / 128, NHEADS, BATCH);
    attn_mma<<<ga, 256, SMEM_ATTN>>>(qp, kp, vp, ct16);

    gemm_o<<<dim3(D_MODEL / 128, NTOK / 128), 256, SMEM_GEMM>>>(
        ct16, w16 + 3 * WSZ, bo, out);
}